// round 10
// baseline (speedup 1.0000x reference)
#include <cuda_runtime.h>
#include <cuda_bf16.h>
#include <cstdint>

#define D 128
#define MAXNZ 512

// ---------------------------------------------------------------------------
// Fused kernel: one CTA per batch row, 128 threads.
//   1) scan F[uid] (float4), compact nonzeros (idx,w) into smem
//   2) aggregate: thread d: s_agg[d] = sum_j w_j * E[idx_j][d]
//   3) linear (warp-cooperative, no W staging):
//        warp w computes out dims 32w..32w+31.
//        lane holds a4 = s_agg4[lane] (invariant);
//        per dim: coalesced LDG.128 of W row (L1-resident), 4-FMA dot,
//        butterfly shfl reduce, keep result in lane i; coalesced STG.
// Small smem (~4.7KB) + reg cap -> ~12 CTAs/SM: scan keeps DRAM MLP,
// linear fills idle issue slots. No second kernel launch.
// ---------------------------------------------------------------------------
__global__ __launch_bounds__(128, 12) void fused_kernel(
    const int*   __restrict__ ids,
    const float* __restrict__ F,
    const float* __restrict__ E,
    const float* __restrict__ W,
    const float* __restrict__ bias,
    float*       __restrict__ out,
    int n_total)
{
    __shared__ int   s_idx[MAXNZ];
    __shared__ float s_w[MAXNZ];
    __shared__ __align__(16) float s_agg[D];
    __shared__ int   s_cnt;

    const int tid = threadIdx.x;
    if (tid == 0) s_cnt = 0;
    __syncthreads();

    const int uid = ids[blockIdx.x];
    const float* __restrict__ row = F + (size_t)uid * (size_t)n_total;

    // ---- 1) scan + compact ----
    if (((n_total & 3) == 0) && ((((uintptr_t)row) & 15) == 0)) {
        const float4* __restrict__ row4 = (const float4*)row;
        const int nvec = n_total >> 2;
        for (int i = tid; i < nvec; i += 128) {
            float4 v = row4[i];
            if (v.x != 0.0f) { int p = atomicAdd(&s_cnt, 1); if (p < MAXNZ) { s_idx[p] = 4*i + 0; s_w[p] = v.x; } }
            if (v.y != 0.0f) { int p = atomicAdd(&s_cnt, 1); if (p < MAXNZ) { s_idx[p] = 4*i + 1; s_w[p] = v.y; } }
            if (v.z != 0.0f) { int p = atomicAdd(&s_cnt, 1); if (p < MAXNZ) { s_idx[p] = 4*i + 2; s_w[p] = v.z; } }
            if (v.w != 0.0f) { int p = atomicAdd(&s_cnt, 1); if (p < MAXNZ) { s_idx[p] = 4*i + 3; s_w[p] = v.w; } }
        }
    } else {
        for (int i = tid; i < n_total; i += 128) {
            float v = row[i];
            if (v != 0.0f) { int p = atomicAdd(&s_cnt, 1); if (p < MAXNZ) { s_idx[p] = i; s_w[p] = v; } }
        }
    }
    __syncthreads();

    // ---- 2) aggregate (thread d owns dim d) ----
    {
        const int cnt = min(s_cnt, MAXNZ);
        const int d = tid;
        float acc = 0.0f;
        int j = 0;
        for (; j + 4 <= cnt; j += 4) {
            const float w0 = s_w[j + 0], w1 = s_w[j + 1], w2 = s_w[j + 2], w3 = s_w[j + 3];
            const float e0 = E[(size_t)s_idx[j + 0] * D + d];
            const float e1 = E[(size_t)s_idx[j + 1] * D + d];
            const float e2 = E[(size_t)s_idx[j + 2] * D + d];
            const float e3 = E[(size_t)s_idx[j + 3] * D + d];
            acc += w0 * e0;
            acc += w1 * e1;
            acc += w2 * e2;
            acc += w3 * e3;
        }
        for (; j < cnt; ++j)
            acc += s_w[j] * E[(size_t)s_idx[j] * D + d];
        s_agg[tid] = acc;
    }
    __syncthreads();

    // ---- 3) warp-cooperative linear ----
    {
        const int wid  = tid >> 5;
        const int lane = tid & 31;
        const float4 a = ((const float4*)s_agg)[lane];   // invariant across dims
        const float4* __restrict__ W4 = (const float4*)W;

        float res = 0.0f;
#pragma unroll 4
        for (int i = 0; i < 32; ++i) {
            const int d = (wid << 5) + i;
            const float4 w = W4[(size_t)d * (D / 4) + lane];   // coalesced, L1-hot
            float p = w.x * a.x;
            p += w.y * a.y;
            p += w.z * a.z;
            p += w.w * a.w;
            // butterfly reduce across the warp
            p += __shfl_xor_sync(0xffffffffu, p, 16);
            p += __shfl_xor_sync(0xffffffffu, p, 8);
            p += __shfl_xor_sync(0xffffffffu, p, 4);
            p += __shfl_xor_sync(0xffffffffu, p, 2);
            p += __shfl_xor_sync(0xffffffffu, p, 1);
            if (lane == i) res = p;                       // keep dim i in lane i
        }
        const int d = (wid << 5) + lane;
        out[(size_t)blockIdx.x * D + d] = res + bias[d];  // coalesced
    }
}

extern "C" void kernel_launch(void* const* d_in, const int* in_sizes, int n_in,
                              void* d_out, int out_size)
{
    const int*   ids  = (const int*)  d_in[0];
    const float* F    = (const float*)d_in[1];
    const float* E    = (const float*)d_in[2];
    const float* W    = (const float*)d_in[3];
    const float* bias = (const float*)d_in[4];
    float* out = (float*)d_out;

    const int B       = in_sizes[0];
    const int n_total = in_sizes[2] / D;

    fused_kernel<<<B, 128>>>(ids, F, E, W, bias, out, n_total);
}

// round 11
// speedup vs baseline: 1.0476x; 1.0476x over previous
#include <cuda_runtime.h>
#include <cuda_bf16.h>
#include <cstdint>

#define D 128
#define MAXNZ 256          // row degree ~Poisson(32); far below 256
#define PART_BYTES (4 * 32 * 33 * 4)   // s_part: 4 warps x 32 dims x 33 pad

// ---------------------------------------------------------------------------
// Fused kernel: one CTA per batch row, 128 threads, ~17.6KB smem (~13 CTA/SM).
//   1) scan F[uid] (float4), compact nonzeros (idx,w) into smem
//   2) aggregate: thread d: s_agg[d] = sum_j w_j * E[idx_j][d]
//   3) linear via smem transpose-reduce (NO dependent shfl chains):
//      warp w, dims 32w..32w+31:
//        lane holds a4 = s_agg4[lane];
//        32 indep iters: LDG.128 W row (L1-hot) + 4 FMA + conflict-free STS
//        then lane=dim sums its 32 partials (conflict-free LDS, 4 accumulators)
//      s_part aliases the (dead) scan-list buffer.
// ---------------------------------------------------------------------------
__global__ __launch_bounds__(128, 12) void fused_kernel(
    const int*   __restrict__ ids,
    const float* __restrict__ F,
    const float* __restrict__ E,
    const float* __restrict__ W,
    const float* __restrict__ bias,
    float*       __restrict__ out,
    int n_total)
{
    __shared__ __align__(16) unsigned char s_buf[PART_BYTES];  // lists, then s_part
    __shared__ __align__(16) float s_agg[D];
    __shared__ int s_cnt;

    int*   __restrict__ s_idx = (int*)s_buf;
    float* __restrict__ s_w   = (float*)(s_buf + MAXNZ * 4);

    const int tid = threadIdx.x;
    if (tid == 0) s_cnt = 0;
    __syncthreads();

    const int uid = ids[blockIdx.x];
    const float* __restrict__ row = F + (size_t)uid * (size_t)n_total;

    // ---- 1) scan + compact ----
    if (((n_total & 3) == 0) && ((((uintptr_t)row) & 15) == 0)) {
        const float4* __restrict__ row4 = (const float4*)row;
        const int nvec = n_total >> 2;
        for (int i = tid; i < nvec; i += 128) {
            float4 v = row4[i];
            if (v.x != 0.0f) { int p = atomicAdd(&s_cnt, 1); if (p < MAXNZ) { s_idx[p] = 4*i + 0; s_w[p] = v.x; } }
            if (v.y != 0.0f) { int p = atomicAdd(&s_cnt, 1); if (p < MAXNZ) { s_idx[p] = 4*i + 1; s_w[p] = v.y; } }
            if (v.z != 0.0f) { int p = atomicAdd(&s_cnt, 1); if (p < MAXNZ) { s_idx[p] = 4*i + 2; s_w[p] = v.z; } }
            if (v.w != 0.0f) { int p = atomicAdd(&s_cnt, 1); if (p < MAXNZ) { s_idx[p] = 4*i + 3; s_w[p] = v.w; } }
        }
    } else {
        for (int i = tid; i < n_total; i += 128) {
            float v = row[i];
            if (v != 0.0f) { int p = atomicAdd(&s_cnt, 1); if (p < MAXNZ) { s_idx[p] = i; s_w[p] = v; } }
        }
    }
    __syncthreads();

    // ---- 2) aggregate (thread d owns dim d) ----
    {
        const int cnt = min(s_cnt, MAXNZ);
        const int d = tid;
        float acc = 0.0f;
        int j = 0;
        for (; j + 4 <= cnt; j += 4) {
            const float w0 = s_w[j + 0], w1 = s_w[j + 1], w2 = s_w[j + 2], w3 = s_w[j + 3];
            const float e0 = E[(size_t)s_idx[j + 0] * D + d];
            const float e1 = E[(size_t)s_idx[j + 1] * D + d];
            const float e2 = E[(size_t)s_idx[j + 2] * D + d];
            const float e3 = E[(size_t)s_idx[j + 3] * D + d];
            acc += w0 * e0;
            acc += w1 * e1;
            acc += w2 * e2;
            acc += w3 * e3;
        }
        for (; j < cnt; ++j)
            acc += s_w[j] * E[(size_t)s_idx[j] * D + d];
        s_agg[tid] = acc;
    }
    __syncthreads();   // lists dead from here; s_buf becomes s_part

    // ---- 3) linear: smem transpose-reduce ----
    {
        float* __restrict__ s_part = (float*)s_buf;      // [4][32][33]
        const int wid  = tid >> 5;
        const int lane = tid & 31;
        const float4 a = ((const float4*)s_agg)[lane];   // k-slice 4*lane..4*lane+3
        const float4* __restrict__ W4 = (const float4*)W;
        float* __restrict__ part = s_part + wid * (32 * 33);

#pragma unroll 4
        for (int i = 0; i < 32; ++i) {                   // independent iterations
            const float4 w = W4[(size_t)(wid * 32 + i) * (D / 4) + lane];  // coalesced
            float p = w.x * a.x;
            p += w.y * a.y;
            p += w.z * a.z;
            p += w.w * a.w;
            part[i * 33 + lane] = p;                     // bank (i+lane)%32: conflict-free
        }
        __syncwarp();

        // lane = dim: sum 32 partials, 4-way accumulator split
        float s0 = 0.f, s1 = 0.f, s2 = 0.f, s3 = 0.f;
        const float* __restrict__ myrow = part + lane * 33;
#pragma unroll
        for (int l = 0; l < 32; l += 4) {                // bank (lane+l)%32: conflict-free
            s0 += myrow[l + 0];
            s1 += myrow[l + 1];
            s2 += myrow[l + 2];
            s3 += myrow[l + 3];
        }
        const int d = (wid << 5) + lane;
        out[(size_t)blockIdx.x * D + d] = (s0 + s1) + (s2 + s3) + bias[d];
    }
}

extern "C" void kernel_launch(void* const* d_in, const int* in_sizes, int n_in,
                              void* d_out, int out_size)
{
    const int*   ids  = (const int*)  d_in[0];
    const float* F    = (const float*)d_in[1];
    const float* E    = (const float*)d_in[2];
    const float* W    = (const float*)d_in[3];
    const float* bias = (const float*)d_in[4];
    float* out = (float*)d_out;

    const int B       = in_sizes[0];
    const int n_total = in_sizes[2] / D;

    fused_kernel<<<B, 128>>>(ids, F, E, W, bias, out, n_total);
}

// round 12
// speedup vs baseline: 1.0521x; 1.0043x over previous
#include <cuda_runtime.h>
#include <cuda_bf16.h>
#include <cstdint>

#define D 128
#define MAXNZ 256          // row degree ~Poisson(32); max << 256
#define PART_BYTES (4 * 32 * 33 * 4)   // s_part: 4 warps x 32 dims x 33 pad

// ---------------------------------------------------------------------------
// Fused kernel: one CTA per batch row, 128 threads, ~17.6KB smem.
//   1) scan F[uid]: manually batched 4x LDG.128 before tests -> MLP>=4/thread
//   2) aggregate: unroll-8, 8 independent L2 loads in flight
//   3) linear: smem transpose-reduce (conflict-free, no dependent chains)
// __launch_bounds__(128,8): 64-reg budget so the load batching survives.
// ---------------------------------------------------------------------------
__global__ __launch_bounds__(128, 8) void fused_kernel(
    const int*   __restrict__ ids,
    const float* __restrict__ F,
    const float* __restrict__ E,
    const float* __restrict__ W,
    const float* __restrict__ bias,
    float*       __restrict__ out,
    int n_total)
{
    __shared__ __align__(16) unsigned char s_buf[PART_BYTES];  // lists, then s_part
    __shared__ __align__(16) float s_agg[D];
    __shared__ int s_cnt;

    int*   __restrict__ s_idx = (int*)s_buf;
    float* __restrict__ s_w   = (float*)(s_buf + MAXNZ * 4);

    const int tid = threadIdx.x;
    if (tid == 0) s_cnt = 0;
    __syncthreads();

    const int uid = ids[blockIdx.x];
    const float* __restrict__ row = F + (size_t)uid * (size_t)n_total;

    // ---- 1) scan + compact (batched loads for MLP) ----
    if (((n_total & 3) == 0) && ((((uintptr_t)row) & 15) == 0)) {
        const float4* __restrict__ row4 = (const float4*)row;
        const int nvec  = n_total >> 2;
        const int nmain = nvec & ~511;         // multiple of 4*128

        for (int i = tid; i < nmain; i += 512) {
            // 4 independent 16B loads in flight before any data-dependent work
            const float4 v0 = row4[i];
            const float4 v1 = row4[i + 128];
            const float4 v2 = row4[i + 256];
            const float4 v3 = row4[i + 384];
#define EMIT(v, base) \
            if ((v).x != 0.0f) { int p = atomicAdd(&s_cnt, 1); if (p < MAXNZ) { s_idx[p] = (base) + 0; s_w[p] = (v).x; } } \
            if ((v).y != 0.0f) { int p = atomicAdd(&s_cnt, 1); if (p < MAXNZ) { s_idx[p] = (base) + 1; s_w[p] = (v).y; } } \
            if ((v).z != 0.0f) { int p = atomicAdd(&s_cnt, 1); if (p < MAXNZ) { s_idx[p] = (base) + 2; s_w[p] = (v).z; } } \
            if ((v).w != 0.0f) { int p = atomicAdd(&s_cnt, 1); if (p < MAXNZ) { s_idx[p] = (base) + 3; s_w[p] = (v).w; } }
            EMIT(v0, 4 * i)
            EMIT(v1, 4 * (i + 128))
            EMIT(v2, 4 * (i + 256))
            EMIT(v3, 4 * (i + 384))
        }
        for (int i = nmain + tid; i < nvec; i += 128) {
            const float4 v = row4[i];
            EMIT(v, 4 * i)
        }
#undef EMIT
    } else {
        for (int i = tid; i < n_total; i += 128) {
            float v = row[i];
            if (v != 0.0f) { int p = atomicAdd(&s_cnt, 1); if (p < MAXNZ) { s_idx[p] = i; s_w[p] = v; } }
        }
    }
    __syncthreads();

    // ---- 2) aggregate (thread d owns dim d; 8 loads in flight) ----
    {
        const int cnt = min(s_cnt, MAXNZ);
        const int d = tid;
        float acc = 0.0f;
        int j = 0;
        for (; j + 8 <= cnt; j += 8) {
            const float e0 = E[(size_t)s_idx[j + 0] * D + d];
            const float e1 = E[(size_t)s_idx[j + 1] * D + d];
            const float e2 = E[(size_t)s_idx[j + 2] * D + d];
            const float e3 = E[(size_t)s_idx[j + 3] * D + d];
            const float e4 = E[(size_t)s_idx[j + 4] * D + d];
            const float e5 = E[(size_t)s_idx[j + 5] * D + d];
            const float e6 = E[(size_t)s_idx[j + 6] * D + d];
            const float e7 = E[(size_t)s_idx[j + 7] * D + d];
            acc += s_w[j + 0] * e0; acc += s_w[j + 1] * e1;
            acc += s_w[j + 2] * e2; acc += s_w[j + 3] * e3;
            acc += s_w[j + 4] * e4; acc += s_w[j + 5] * e5;
            acc += s_w[j + 6] * e6; acc += s_w[j + 7] * e7;
        }
        for (; j < cnt; ++j)
            acc += s_w[j] * E[(size_t)s_idx[j] * D + d];
        s_agg[tid] = acc;
    }
    __syncthreads();   // lists dead; s_buf becomes s_part

    // ---- 3) linear: smem transpose-reduce ----
    {
        float* __restrict__ s_part = (float*)s_buf;      // [4][32][33]
        const int wid  = tid >> 5;
        const int lane = tid & 31;
        const float4 a = ((const float4*)s_agg)[lane];
        const float4* __restrict__ W4 = (const float4*)W;
        float* __restrict__ part = s_part + wid * (32 * 33);

#pragma unroll 4
        for (int i = 0; i < 32; ++i) {                   // independent iterations
            const float4 w = W4[(size_t)(wid * 32 + i) * (D / 4) + lane];  // coalesced, L1-hot
            float p = w.x * a.x;
            p += w.y * a.y;
            p += w.z * a.z;
            p += w.w * a.w;
            part[i * 33 + lane] = p;                     // conflict-free
        }
        __syncwarp();

        float s0 = 0.f, s1 = 0.f, s2 = 0.f, s3 = 0.f;
        const float* __restrict__ myrow = part + lane * 33;
#pragma unroll
        for (int l = 0; l < 32; l += 4) {                // conflict-free
            s0 += myrow[l + 0];
            s1 += myrow[l + 1];
            s2 += myrow[l + 2];
            s3 += myrow[l + 3];
        }
        const int d = (wid << 5) + lane;
        out[(size_t)blockIdx.x * D + d] = (s0 + s1) + (s2 + s3) + bias[d];
    }
}

extern "C" void kernel_launch(void* const* d_in, const int* in_sizes, int n_in,
                              void* d_out, int out_size)
{
    const int*   ids  = (const int*)  d_in[0];
    const float* F    = (const float*)d_in[1];
    const float* E    = (const float*)d_in[2];
    const float* W    = (const float*)d_in[3];
    const float* bias = (const float*)d_in[4];
    float* out = (float*)d_out;

    const int B       = in_sizes[0];
    const int n_total = in_sizes[2] / D;

    fused_kernel<<<B, 128>>>(ids, F, E, W, bias, out, n_total);
}

// round 13
// speedup vs baseline: 1.3292x; 1.2634x over previous
#include <cuda_runtime.h>
#include <cuda_bf16.h>
#include <cstdint>

#define D 128
#define MAXNZ 512
#define BM 16              // batch rows per lin CTA
#define DN 32              // output cols per lin CTA
#define SWS 132            // smem W row stride (floats) -> conflict-free LDS.128
#define MAXB 4096

__device__ float g_agg[(size_t)MAXB * D];

// ---------------------------------------------------------------------------
// Kernel 1: scan F[uid] + sparse aggregate vs E (R3 structure).
// F loads use __ldcs (evict-first): the 83MB stream passes through L2 without
// evicting W / E / the agg rows that kernel 2 needs — kernel 2 stays L2-warm.
// ---------------------------------------------------------------------------
__global__ __launch_bounds__(128) void agg_kernel(
    const int* __restrict__ ids,
    const float* __restrict__ F,
    const float* __restrict__ E,
    int n_total,
    float* __restrict__ agg)
{
    __shared__ int   s_idx[MAXNZ];
    __shared__ float s_w[MAXNZ];
    __shared__ int   s_cnt;

    const int tid = threadIdx.x;
    if (tid == 0) s_cnt = 0;
    __syncthreads();

    const int uid = ids[blockIdx.x];
    const float* __restrict__ row = F + (size_t)uid * (size_t)n_total;

    if (((n_total & 3) == 0) && ((((uintptr_t)row) & 15) == 0)) {
        const float4* __restrict__ row4 = (const float4*)row;
        const int nvec = n_total >> 2;
        for (int i = tid; i < nvec; i += 128) {
            float4 v = __ldcs(&row4[i]);
            if (v.x != 0.0f) { int p = atomicAdd(&s_cnt, 1); if (p < MAXNZ) { s_idx[p] = 4*i + 0; s_w[p] = v.x; } }
            if (v.y != 0.0f) { int p = atomicAdd(&s_cnt, 1); if (p < MAXNZ) { s_idx[p] = 4*i + 1; s_w[p] = v.y; } }
            if (v.z != 0.0f) { int p = atomicAdd(&s_cnt, 1); if (p < MAXNZ) { s_idx[p] = 4*i + 2; s_w[p] = v.z; } }
            if (v.w != 0.0f) { int p = atomicAdd(&s_cnt, 1); if (p < MAXNZ) { s_idx[p] = 4*i + 3; s_w[p] = v.w; } }
        }
    } else {
        for (int i = tid; i < n_total; i += 128) {
            float v = __ldcs(&row[i]);
            if (v != 0.0f) { int p = atomicAdd(&s_cnt, 1); if (p < MAXNZ) { s_idx[p] = i; s_w[p] = v; } }
        }
    }
    __syncthreads();

    const int cnt = min(s_cnt, MAXNZ);
    const int d = tid;
    float acc = 0.0f;

    int j = 0;
    for (; j + 4 <= cnt; j += 4) {
        const float w0 = s_w[j + 0], w1 = s_w[j + 1], w2 = s_w[j + 2], w3 = s_w[j + 3];
        const float e0 = E[(size_t)s_idx[j + 0] * D + d];
        const float e1 = E[(size_t)s_idx[j + 1] * D + d];
        const float e2 = E[(size_t)s_idx[j + 2] * D + d];
        const float e3 = E[(size_t)s_idx[j + 3] * D + d];
        acc += w0 * e0;
        acc += w1 * e1;
        acc += w2 * e2;
        acc += w3 * e3;
    }
    for (; j < cnt; ++j)
        acc += s_w[j] * E[(size_t)s_idx[j] * D + d];

    agg[(size_t)blockIdx.x * D + d] = acc;
}

// ---------------------------------------------------------------------------
// Kernel 2 (R9 d-split, best measured): out = agg @ W^T + bias.
// CTA = 16 rows x 32 cols, grid = (B/16, 4), 128 threads, ~25KB smem.
// With a clean L2 (thanks to __ldcs above) staging is L2-latency, not DRAM.
// ---------------------------------------------------------------------------
__global__ __launch_bounds__(128) void lin_kernel(
    const float* __restrict__ agg,
    const float* __restrict__ W,
    const float* __restrict__ bias,
    float* __restrict__ out,
    int B)
{
    __shared__ __align__(16) float sW[DN * SWS];   // [32][132]
    __shared__ __align__(16) float sA[BM * D];     // [16][128]

    const int tid = threadIdx.x;
    const int tx  = tid & 31;
    const int ty  = tid >> 5;
    const int row0 = blockIdx.x * BM;
    const int d0   = blockIdx.y * DN;

    {
        const float4* __restrict__ W4 = (const float4*)W;
        float4* __restrict__ sW4 = (float4*)sW;
#pragma unroll
        for (int t = 0; t < 8; ++t) {
            const int i4  = tid + t * 128;     // 0..1023
            const int c   = i4 >> 5;
            const int k4c = i4 & 31;
            sW4[c * (SWS / 4) + k4c] = W4[(size_t)(d0 + c) * (D / 4) + k4c];
        }
    }
    {
        const float4* __restrict__ A4 = (const float4*)(agg + (size_t)row0 * D);
        float4* __restrict__ sA4 = (float4*)sA;
#pragma unroll
        for (int t = 0; t < 4; ++t) {
            const int i4 = tid + t * 128;
            sA4[i4] = A4[i4];
        }
    }
    __syncthreads();

    float acc[4] = {0.f, 0.f, 0.f, 0.f};
    const float4* __restrict__ a4 = (const float4*)sA;
    const float4* __restrict__ w4 = ((const float4*)sW) + tx * (SWS / 4);

#pragma unroll 8
    for (int k4 = 0; k4 < D / 4; ++k4) {
        const float4 w = w4[k4];                         // conflict-free
#pragma unroll
        for (int r = 0; r < 4; ++r) {
            const float4 a = a4[(4 * ty + r) * (D / 4) + k4];  // broadcast
            acc[r] += a.x * w.x;
            acc[r] += a.y * w.y;
            acc[r] += a.z * w.z;
            acc[r] += a.w * w.w;
        }
    }

    const float b = bias[d0 + tx];
#pragma unroll
    for (int r = 0; r < 4; ++r) {
        const int rr = row0 + 4 * ty + r;
        if (rr < B)
            out[(size_t)rr * D + d0 + tx] = acc[r] + b;
    }
}

extern "C" void kernel_launch(void* const* d_in, const int* in_sizes, int n_in,
                              void* d_out, int out_size)
{
    const int*   ids  = (const int*)  d_in[0];
    const float* F    = (const float*)d_in[1];
    const float* E    = (const float*)d_in[2];
    const float* W    = (const float*)d_in[3];
    const float* bias = (const float*)d_in[4];
    float* out = (float*)d_out;

    const int B       = in_sizes[0];
    const int n_total = in_sizes[2] / D;

    float* agg;
    cudaGetSymbolAddress((void**)&agg, g_agg);

    agg_kernel<<<B, 128>>>(ids, F, E, n_total, agg);

    dim3 grid2((B + BM - 1) / BM, D / DN);
    lin_kernel<<<grid2, 128>>>(agg, W, bias, out, B);
}